// round 13
// baseline (speedup 1.0000x reference)
#include <cuda_runtime.h>
#include <cuda_fp16.h>
#include <math.h>
#include <stdint.h>

#define DIM 1024
#define BB 4
#define SS 2048
#define NH 16
#define HD 64
#define MROWS (BB*SS)   // 8192
#define LOG2E 1.44269504088896340736f

// ---------------------------------------------------------------------------
// Scratch (device globals; no allocation allowed) — fp16 operands everywhere
// ---------------------------------------------------------------------------
__device__ __half g_Q[BB*NH*SS*HD];   // [b,h,s,d] projected Q (x 0.125*log2e)
__device__ __half g_K[BB*NH*SS*HD];
__device__ __half g_V[BB*NH*SS*HD];
__device__ __half g_Z[MROWS*DIM];     // attention out
__device__ __half g_RQ[MROWS*DIM];    // fp16 inputs
__device__ __half g_RK[MROWS*DIM];
__device__ __half g_RV[MROWS*DIM];
__device__ __half g_RW[4][DIM*DIM];   // fp16 weights
__device__ int    g_maskflag;         // zero-init; reset by out_gemm each run

// ---------------------------------------------------------------------------
// Helpers (compute_103-legal, sm_80-era PTX)
// ---------------------------------------------------------------------------
__device__ __forceinline__ uint32_t smem_u32(const void* p) {
    uint32_t a;
    asm("{ .reg .u64 t; cvta.to.shared.u64 t, %1; cvt.u32.u64 %0, t; }" : "=r"(a) : "l"(p));
    return a;
}
__device__ __forceinline__ void cp16(uint32_t dst, const void* src) {
    asm volatile("cp.async.cg.shared.global [%0], [%1], 16;" :: "r"(dst), "l"(src));
}
#define CP_COMMIT() asm volatile("cp.async.commit_group;" ::: "memory")

__device__ __forceinline__ void mma_f16(float d[4], const uint32_t a[4], const uint32_t b[2]) {
    asm volatile(
        "mma.sync.aligned.m16n8k16.row.col.f32.f16.f16.f32 "
        "{%0,%1,%2,%3}, {%4,%5,%6,%7}, {%8,%9}, {%0,%1,%2,%3};"
        : "+f"(d[0]), "+f"(d[1]), "+f"(d[2]), "+f"(d[3])
        : "r"(a[0]), "r"(a[1]), "r"(a[2]), "r"(a[3]), "r"(b[0]), "r"(b[1]));
}
__device__ __forceinline__ void ldsm_x4(uint32_t r[4], uint32_t addr) {
    asm volatile("ldmatrix.sync.aligned.m8n8.x4.shared.b16 {%0,%1,%2,%3}, [%4];"
                 : "=r"(r[0]), "=r"(r[1]), "=r"(r[2]), "=r"(r[3]) : "r"(addr));
}
__device__ __forceinline__ void ldsm_x4_t(uint32_t r[4], uint32_t addr) {
    asm volatile("ldmatrix.sync.aligned.m8n8.x4.trans.shared.b16 {%0,%1,%2,%3}, [%4];"
                 : "=r"(r[0]), "=r"(r[1]), "=r"(r[2]), "=r"(r[3]) : "r"(addr));
}
__device__ __forceinline__ uint32_t pack_h2(float x, float y) {
    __half2 h = __float22half2_rn(make_float2(x, y));
    return *(uint32_t*)&h;
}

// ---------------------------------------------------------------------------
// Merged f32->fp16 convert (q,k,v,W*) + mask scan. grid (2048,1,8), 256 thr.
// ---------------------------------------------------------------------------
__global__ __launch_bounds__(256)
void round_all(const float* __restrict__ q, const float* __restrict__ k,
               const float* __restrict__ v, const float* __restrict__ Wq,
               const float* __restrict__ Wk, const float* __restrict__ Wv,
               const float* __restrict__ Wd, const float* __restrict__ mask)
{
    const int z = blockIdx.z;
    const int tid = threadIdx.x;
    if (z == 7) {   // mask scan
        const float4* m4 = (const float4*)mask;
        const size_t base = (size_t)blockIdx.x * 2048 + tid;
        bool nz = false;
#pragma unroll
        for (int i = 0; i < 8; i++) {
            float4 vv = m4[base + (size_t)i * 256];
            nz |= (vv.x != 0.f) | (vv.y != 0.f) | (vv.z != 0.f) | (vv.w != 0.f);
        }
        if (__syncthreads_or(nz) && tid == 0) atomicExch(&g_maskflag, 1);
        return;
    }
    const float* src; __half* dst; int nblk;
    switch (z) {
        case 0: src = q;  dst = g_RQ;    nblk = 2048; break;
        case 1: src = k;  dst = g_RK;    nblk = 2048; break;
        case 2: src = v;  dst = g_RV;    nblk = 2048; break;
        case 3: src = Wq; dst = g_RW[0]; nblk = 256;  break;
        case 4: src = Wk; dst = g_RW[1]; nblk = 256;  break;
        case 5: src = Wv; dst = g_RW[2]; nblk = 256;  break;
        default: src = Wd; dst = g_RW[3]; nblk = 256; break;
    }
    if (blockIdx.x >= (unsigned)nblk) return;
    const float4* s4 = (const float4*)src;
    __half2* d2 = (__half2*)dst;
    const size_t base = (size_t)blockIdx.x * 1024 + tid;
#pragma unroll
    for (int i = 0; i < 4; i++) {
        const size_t f = base + (size_t)i * 256;
        float4 vv = s4[f];
        d2[2 * f]     = __float22half2_rn(make_float2(vv.x, vv.y));
        d2[2 * f + 1] = __float22half2_rn(make_float2(vv.z, vv.w));
    }
}

// ---------------------------------------------------------------------------
// fp16 GEMM core: BM=BN=128, BK=32 halves, 128 thr (2x2 warps, 64x64 warp
// tile), 4-stage cp.async pipe, CROSS-K-TILE fragment software pipelining:
// frags for tile kt+1 are ldsm'd during tile kt's mma burst.
// ---------------------------------------------------------------------------
#define PSTH 40
#define STG_H (2 * 128 * PSTH)
#define STG_B (STG_H * 2)
#define GEMM_SMEM (4 * STG_B)         // 81920 bytes

template<int LAYOUT>
__device__ __forceinline__
void gemm_core(const __half* __restrict__ A, const __half* __restrict__ W,
               void* __restrict__ Cv, float scale, char* smc)
{
    const int tid = threadIdx.x;
    const int lane = tid & 31, wid = tid >> 5;
    const int wr = wid >> 1, wc = wid & 1;
    const int r0 = lane >> 2, c0 = lane & 3;
    const int g = lane >> 3, lr = lane & 7;
    const int row0 = blockIdx.x * 128, col0 = blockIdx.y * 128;
    const uint32_t smb = smem_u32(smc);

    const int aoff = (wr * 64 + lr + (g & 1) * 8) * PSTH + (g >> 1) * 8;
    const int boff = (wc * 64 + lr + (g >> 1) * 8) * PSTH + (g & 1) * 8;

    float acc[4][8][4];
#pragma unroll
    for (int mt = 0; mt < 4; mt++)
#pragma unroll
        for (int nt = 0; nt < 8; nt++)
#pragma unroll
            for (int j = 0; j < 4; j++) acc[mt][nt][j] = 0.f;

    auto load_stage = [&](int kt, int s) {
        uint32_t a_s = smb + s * STG_B;
        uint32_t b_s = a_s + 128 * PSTH * 2;
#pragma unroll
        for (int i = 0; i < 4; i++) {
            int c = tid + 128 * i;
            int row = c >> 2, c4 = c & 3;
            uint32_t so = (uint32_t)(row * PSTH + c4 * 8) * 2;
            cp16(a_s + so, A + (size_t)(row0 + row) * DIM + kt * 32 + c4 * 8);
            cp16(b_s + so, W + (size_t)(col0 + row) * DIM + kt * 32 + c4 * 8);
        }
    };

    // fragment loader for a whole k-tile (2 k16 chunks) from stage s
    uint32_t af[2][2][4][4], bf[2][2][4][4];   // [buf][ks][mt/p][frag]
    auto load_frags = [&](int s, int buf) {
        const uint32_t a_s = smb + s * STG_B;
        const uint32_t b_s = a_s + 128 * PSTH * 2;
#pragma unroll
        for (int ks = 0; ks < 2; ks++) {
            const int kb = ks * 16;
#pragma unroll
            for (int mt = 0; mt < 4; mt++)
                ldsm_x4(af[buf][ks][mt], a_s + (uint32_t)(aoff + mt * 16 * PSTH + kb) * 2);
#pragma unroll
            for (int p = 0; p < 4; p++)
                ldsm_x4(bf[buf][ks][p], b_s + (uint32_t)(boff + p * 16 * PSTH + kb) * 2);
        }
    };

    load_stage(0, 0); CP_COMMIT();
    load_stage(1, 1); CP_COMMIT();
    load_stage(2, 2); CP_COMMIT();
    asm volatile("cp.async.wait_group 1;" ::: "memory");   // tiles 0,1 resident
    __syncthreads();
    load_frags(0, 0);                                      // frags for tile 0

    const int NT = DIM / 32;                     // 32
    for (int kt = 0; kt < NT; kt++) {
        const int cur = kt & 1, nxt = cur ^ 1;
        // frags for tile kt+1 (resident by wait at end of prev iter)
        if (kt + 1 < NT) load_frags((kt + 1) & 3, nxt);
        __syncthreads();   // all warps done reading stage (kt-1)&3 (ldsm at kt-2)
        if (kt + 3 < NT) load_stage(kt + 3, (kt + 3) & 3);
        CP_COMMIT();

        // 128-mma burst on pre-loaded fragments
#pragma unroll
        for (int ks = 0; ks < 2; ks++)
#pragma unroll
            for (int nt = 0; nt < 8; nt++) {
                const uint32_t bfr[2] = { bf[cur][ks][nt >> 1][(nt & 1) * 2],
                                          bf[cur][ks][nt >> 1][(nt & 1) * 2 + 1] };
#pragma unroll
                for (int mt = 0; mt < 4; mt++)
                    mma_f16(acc[mt][nt], af[cur][ks][mt], bfr);
            }
        asm volatile("cp.async.wait_group 1;" ::: "memory");   // tile kt+2 resident
    }

#pragma unroll
    for (int mt = 0; mt < 4; mt++) {
        const int rA = row0 + wr * 64 + mt * 16 + r0;
#pragma unroll
        for (int rr = 0; rr < 2; rr++) {
            const int r = rA + rr * 8;
#pragma unroll
            for (int nt = 0; nt < 8; nt++) {
                const int col = col0 + wc * 64 + nt * 8 + 2 * c0;
                float v0 = acc[mt][nt][rr * 2 + 0] * scale;
                float v1 = acc[mt][nt][rr * 2 + 1] * scale;
                if (LAYOUT == 0) {
                    const int b = r >> 11, s = r & (SS - 1);
                    const int h = col >> 6, d = col & 63;
                    __half* C = (__half*)Cv;
                    *(__half2*)(C + ((size_t)((b * NH + h) * SS) + s) * HD + d) =
                        __float22half2_rn(make_float2(v0, v1));
                } else {
                    float* C = (float*)Cv;
                    *(float2*)(C + (size_t)r * DIM + col) = make_float2(v0, v1);
                }
            }
        }
    }
}

__global__ __launch_bounds__(128, 2)
void qkv_gemm()
{
    extern __shared__ char smc[];
    const int z = blockIdx.z;
    if (z == 0)      gemm_core<0>(g_RQ, g_RW[0], g_Q, 0.125f * LOG2E, smc);
    else if (z == 1) gemm_core<0>(g_RK, g_RW[1], g_K, 1.0f, smc);
    else             gemm_core<0>(g_RV, g_RW[2], g_V, 1.0f, smc);
}

__global__ __launch_bounds__(128, 2)
void out_gemm(float* __restrict__ C)
{
    extern __shared__ char smc[];
    gemm_core<1>(g_Z, g_RW[3], C, 1.0f, smc);
    if (blockIdx.x == 0 && blockIdx.y == 0 && threadIdx.x == 0)
        g_maskflag = 0;
}

// ---------------------------------------------------------------------------
// fp16 mma flash attention (round-11, unchanged): 64-key tiles, base-2
// softmax, P in registers, pipelined K/V ldsm.
// ---------------------------------------------------------------------------
#define KSTH 72                       // halves per row (64 + 8)
#define KS_H (64 * KSTH)              // 4608 halves per K (or V) stage
#define ATTN_SMEM ((2*KS_H + 2*KS_H) * 2)   // 36864 B

__global__ __launch_bounds__(128, 2)
void attn_mma(const float* __restrict__ mask)
{
    extern __shared__ char smc[];
    __half* Ks = (__half*)smc;
    __half* Vs = Ks + 2 * KS_H;
    const uint32_t ks_b = smem_u32(Ks);
    const uint32_t vs_b = smem_u32(Vs);

    const int tid = threadIdx.x, lane = tid & 31, w = tid >> 5;
    const int r0 = lane >> 2, c0 = lane & 3;
    const int g = lane >> 3, lr = lane & 7;
    const int q0 = blockIdx.x * 128;
    const int bh = blockIdx.y, b = bh >> 4, h = bh & 15;
    const int use_mask = g_maskflag;

    const int qAoff = (w * 32 + lr + (g & 1) * 8) * KSTH + (g >> 1) * 8;
    const int kBoff = (lr + (g >> 1) * 8) * KSTH + (g & 1) * 8;
    const int vBoff = (lr + (g & 1) * 8) * KSTH + (g >> 1) * 8;

    const __half* Kg0 = g_K + (size_t)bh * SS * HD;
    const __half* Vg0 = g_V + (size_t)bh * SS * HD;

    const __half* Qg = g_Q + ((size_t)bh * SS + q0) * HD;
#pragma unroll
    for (int i = 0; i < 8; i++) {
        int c = tid + 128 * i;
        int row = c >> 3, c8 = c & 7;
        *(uint4*)(Ks + row * KSTH + c8 * 8) = *(const uint4*)(Qg + (size_t)row * HD + c8 * 8);
    }
    __syncthreads();
    uint32_t qf[2][4][4];
#pragma unroll
    for (int mt = 0; mt < 2; mt++)
#pragma unroll
        for (int kc = 0; kc < 4; kc++)
            ldsm_x4(qf[mt][kc], ks_b + (uint32_t)(qAoff + mt * 16 * KSTH + kc * 16) * 2);
    __syncthreads();

    float o[2][8][4];
#pragma unroll
    for (int mt = 0; mt < 2; mt++)
#pragma unroll
        for (int nt = 0; nt < 8; nt++)
#pragma unroll
            for (int j = 0; j < 4; j++) o[mt][nt][j] = 0.f;
    float mrow[2][2], lrow[2][2];
#pragma unroll
    for (int mt = 0; mt < 2; mt++) { mrow[mt][0] = mrow[mt][1] = -INFINITY;
                                     lrow[mt][0] = lrow[mt][1] = 0.f; }

    auto load_kv = [&](int t, int s) {
#pragma unroll
        for (int i = 0; i < 4; i++) {
            int c = tid + 128 * i;
            int row = c >> 3, c8 = c & 7;
            cp16(ks_b + (uint32_t)(s * KS_H + row * KSTH + c8 * 8) * 2,
                 Kg0 + (size_t)(t * 64 + row) * HD + c8 * 8);
            cp16(vs_b + (uint32_t)(s * KS_H + row * KSTH + c8 * 8) * 2,
                 Vg0 + (size_t)(t * 64 + row) * HD + c8 * 8);
        }
    };

    load_kv(0, 0); CP_COMMIT();

    const int NIT = SS / 64;
    for (int it = 0; it < NIT; it++) {
        if (it + 1 < NIT) load_kv(it + 1, (it + 1) & 1);
        CP_COMMIT();
        asm volatile("cp.async.wait_group 1;" ::: "memory");
        __syncthreads();

        const uint32_t ksb = ks_b + (uint32_t)((it & 1) * KS_H) * 2;
        const uint32_t vsb = vs_b + (uint32_t)((it & 1) * KS_H) * 2;

        float s[2][8][4];
#pragma unroll
        for (int mt = 0; mt < 2; mt++)
#pragma unroll
            for (int nt = 0; nt < 8; nt++)
#pragma unroll
                for (int j = 0; j < 4; j++) s[mt][nt][j] = 0.f;

        uint32_t kp[2][4];
        ldsm_x4(kp[0], ksb + (uint32_t)(kBoff) * 2);
#pragma unroll
        for (int idx = 0; idx < 16; idx++) {
            const int kc = idx >> 2, p = idx & 3;
            if (idx + 1 < 16) {
                const int nkc = (idx + 1) >> 2, np = (idx + 1) & 3;
                ldsm_x4(kp[(idx + 1) & 1],
                        ksb + (uint32_t)(kBoff + np * 16 * KSTH + nkc * 16) * 2);
            }
            const uint32_t* kk = kp[idx & 1];
            const uint32_t f0[2] = { kk[0], kk[1] };
            const uint32_t f1[2] = { kk[2], kk[3] };
            mma_f16(s[0][2 * p],     qf[0][kc], f0);
            mma_f16(s[1][2 * p],     qf[1][kc], f0);
            mma_f16(s[0][2 * p + 1], qf[0][kc], f1);
            mma_f16(s[1][2 * p + 1], qf[1][kc], f1);
        }

        if (use_mask) {
#pragma unroll
            for (int mt = 0; mt < 2; mt++) {
                const float* Mg = mask + ((size_t)b * SS + (q0 + w * 32 + mt * 16 + r0)) * SS
                                       + it * 64;
#pragma unroll
                for (int nt = 0; nt < 8; nt++) {
                    float2 mlo = *(const float2*)(Mg + nt * 8 + 2 * c0);
                    float2 mhi = *(const float2*)(Mg + (size_t)8 * SS + nt * 8 + 2 * c0);
                    s[mt][nt][0] = fmaf(mlo.x, LOG2E, s[mt][nt][0]);
                    s[mt][nt][1] = fmaf(mlo.y, LOG2E, s[mt][nt][1]);
                    s[mt][nt][2] = fmaf(mhi.x, LOG2E, s[mt][nt][2]);
                    s[mt][nt][3] = fmaf(mhi.y, LOG2E, s[mt][nt][3]);
                }
            }
        }

        uint32_t pf[2][4][4];
#pragma unroll
        for (int mt = 0; mt < 2; mt++) {
            float mx_lo = -INFINITY, mx_hi = -INFINITY;
#pragma unroll
            for (int nt = 0; nt < 8; nt++) {
                mx_lo = fmaxf(mx_lo, fmaxf(s[mt][nt][0], s[mt][nt][1]));
                mx_hi = fmaxf(mx_hi, fmaxf(s[mt][nt][2], s[mt][nt][3]));
            }
            mx_lo = fmaxf(mx_lo, __shfl_xor_sync(0xffffffffu, mx_lo, 1));
            mx_lo = fmaxf(mx_lo, __shfl_xor_sync(0xffffffffu, mx_lo, 2));
            mx_hi = fmaxf(mx_hi, __shfl_xor_sync(0xffffffffu, mx_hi, 1));
            mx_hi = fmaxf(mx_hi, __shfl_xor_sync(0xffffffffu, mx_hi, 2));
            const float nm_lo = fmaxf(mrow[mt][0], mx_lo);
            const float nm_hi = fmaxf(mrow[mt][1], mx_hi);
            const float corr_lo = exp2f(mrow[mt][0] - nm_lo);
            const float corr_hi = exp2f(mrow[mt][1] - nm_hi);
            mrow[mt][0] = nm_lo; mrow[mt][1] = nm_hi;

            float sum_lo = 0.f, sum_hi = 0.f;
#pragma unroll
            for (int nt = 0; nt < 8; nt++) {
                float p0 = exp2f(s[mt][nt][0] - nm_lo);
                float p1 = exp2f(s[mt][nt][1] - nm_lo);
                float p2 = exp2f(s[mt][nt][2] - nm_hi);
                float p3 = exp2f(s[mt][nt][3] - nm_hi);
                sum_lo += p0 + p1; sum_hi += p2 + p3;
                const int kc = nt >> 1, base = (nt & 1) * 2;
                pf[mt][kc][base + 0] = pack_h2(p0, p1);
                pf[mt][kc][base + 1] = pack_h2(p2, p3);
            }
            sum_lo += __shfl_xor_sync(0xffffffffu, sum_lo, 1);
            sum_lo += __shfl_xor_sync(0xffffffffu, sum_lo, 2);
            sum_hi += __shfl_xor_sync(0xffffffffu, sum_hi, 1);
            sum_hi += __shfl_xor_sync(0xffffffffu, sum_hi, 2);
            lrow[mt][0] = lrow[mt][0] * corr_lo + sum_lo;
            lrow[mt][1] = lrow[mt][1] * corr_hi + sum_hi;
#pragma unroll
            for (int nt = 0; nt < 8; nt++) {
                o[mt][nt][0] *= corr_lo; o[mt][nt][1] *= corr_lo;
                o[mt][nt][2] *= corr_hi; o[mt][nt][3] *= corr_hi;
            }
        }

        uint32_t vp[2][4];
        ldsm_x4_t(vp[0], vsb + (uint32_t)(vBoff) * 2);
#pragma unroll
        for (int idx = 0; idx < 16; idx++) {
            const int kc = idx >> 2, dp = idx & 3;
            if (idx + 1 < 16) {
                const int nkc = (idx + 1) >> 2, ndp = (idx + 1) & 3;
                ldsm_x4_t(vp[(idx + 1) & 1],
                          vsb + (uint32_t)(vBoff + nkc * 16 * KSTH + ndp * 16) * 2);
            }
            const uint32_t* vv = vp[idx & 1];
            const uint32_t f0[2] = { vv[0], vv[1] };
            const uint32_t f1[2] = { vv[2], vv[3] };
            mma_f16(o[0][2 * dp],     pf[0][kc], f0);
            mma_f16(o[1][2 * dp],     pf[1][kc], f0);
            mma_f16(o[0][2 * dp + 1], pf[0][kc], f1);
            mma_f16(o[1][2 * dp + 1], pf[1][kc], f1);
        }
        __syncthreads();
    }

#pragma unroll
    for (int mt = 0; mt < 2; mt++) {
        const float inv_lo = 1.f / lrow[mt][0], inv_hi = 1.f / lrow[mt][1];
        const int qlo = q0 + w * 32 + mt * 16 + r0;
        __half* Zlo = g_Z + ((size_t)b * SS + qlo) * DIM + h * HD;
        __half* Zhi = Zlo + (size_t)8 * DIM;
#pragma unroll
        for (int nt = 0; nt < 8; nt++) {
            const int d = nt * 8 + 2 * c0;
            *(__half2*)(Zlo + d) =
                __float22half2_rn(make_float2(o[mt][nt][0] * inv_lo, o[mt][nt][1] * inv_lo));
            *(__half2*)(Zhi + d) =
                __float22half2_rn(make_float2(o[mt][nt][2] * inv_hi, o[mt][nt][3] * inv_hi));
        }
    }
}

// ---------------------------------------------------------------------------
extern "C" void kernel_launch(void* const* d_in, const int* in_sizes, int n_in,
                              void* d_out, int out_size)
{
    const float* q    = (const float*)d_in[0];
    const float* k    = (const float*)d_in[1];
    const float* v    = (const float*)d_in[2];
    const float* mask = (const float*)d_in[3];
    const float* Wq   = (const float*)d_in[4];
    const float* Wk   = (const float*)d_in[5];
    const float* Wv   = (const float*)d_in[6];
    const float* Wd   = (const float*)d_in[7];

    cudaFuncSetAttribute(qkv_gemm, cudaFuncAttributeMaxDynamicSharedMemorySize, GEMM_SMEM);
    cudaFuncSetAttribute(out_gemm, cudaFuncAttributeMaxDynamicSharedMemorySize, GEMM_SMEM);
    cudaFuncSetAttribute(attn_mma, cudaFuncAttributeMaxDynamicSharedMemorySize, ATTN_SMEM);

    // launch 1: f32->fp16 convert everything + mask scan
    round_all<<<dim3(2048, 1, 8), 256>>>(q, k, v, Wq, Wk, Wv, Wd, mask);

    // launch 2: q/k/v projections (fp16 mma; Q pre-scaled by 0.125*log2e)
    qkv_gemm<<<dim3(MROWS/128, DIM/128, 3), 128, GEMM_SMEM>>>();

    // launch 3: flash attention (fp16 mma, base-2 softmax, P in registers)
    attn_mma<<<dim3(SS/128, BB*NH), 128, ATTN_SMEM>>>(mask);

    // launch 4: output projection, f32 out (+ maskflag reset)
    out_gemm<<<dim3(MROWS/128, DIM/128), 128, GEMM_SMEM>>>((float*)d_out);
}

// round 14
// speedup vs baseline: 1.6469x; 1.6469x over previous
#include <cuda_runtime.h>
#include <cuda_fp16.h>
#include <math.h>
#include <stdint.h>

#define DIM 1024
#define BB 4
#define SS 2048
#define NH 16
#define HD 64
#define MROWS (BB*SS)   // 8192
#define LOG2E 1.44269504088896340736f

// ---------------------------------------------------------------------------
// Scratch (device globals; no allocation allowed) — fp16 operands everywhere
// ---------------------------------------------------------------------------
__device__ __half g_Q[BB*NH*SS*HD];   // [b,h,s,d] projected Q (x 0.125*log2e)
__device__ __half g_K[BB*NH*SS*HD];
__device__ __half g_V[BB*NH*SS*HD];
__device__ __half g_Z[MROWS*DIM];     // attention out
__device__ __half g_RQ[MROWS*DIM];    // fp16 inputs
__device__ __half g_RK[MROWS*DIM];
__device__ __half g_RV[MROWS*DIM];
__device__ __half g_RW[4][DIM*DIM];   // fp16 weights
__device__ int    g_maskflag;         // zero-init; reset by out_gemm each run

// ---------------------------------------------------------------------------
// Helpers (compute_103-legal, sm_80-era PTX)
// ---------------------------------------------------------------------------
__device__ __forceinline__ uint32_t smem_u32(const void* p) {
    uint32_t a;
    asm("{ .reg .u64 t; cvta.to.shared.u64 t, %1; cvt.u32.u64 %0, t; }" : "=r"(a) : "l"(p));
    return a;
}
__device__ __forceinline__ void cp16(uint32_t dst, const void* src) {
    asm volatile("cp.async.cg.shared.global [%0], [%1], 16;" :: "r"(dst), "l"(src));
}
#define CP_COMMIT() asm volatile("cp.async.commit_group;" ::: "memory")

__device__ __forceinline__ void mma_f16(float d[4], const uint32_t a[4], const uint32_t b[2]) {
    asm volatile(
        "mma.sync.aligned.m16n8k16.row.col.f32.f16.f16.f32 "
        "{%0,%1,%2,%3}, {%4,%5,%6,%7}, {%8,%9}, {%0,%1,%2,%3};"
        : "+f"(d[0]), "+f"(d[1]), "+f"(d[2]), "+f"(d[3])
        : "r"(a[0]), "r"(a[1]), "r"(a[2]), "r"(a[3]), "r"(b[0]), "r"(b[1]));
}
__device__ __forceinline__ void ldsm_x4(uint32_t r[4], uint32_t addr) {
    asm volatile("ldmatrix.sync.aligned.m8n8.x4.shared.b16 {%0,%1,%2,%3}, [%4];"
                 : "=r"(r[0]), "=r"(r[1]), "=r"(r[2]), "=r"(r[3]) : "r"(addr));
}
__device__ __forceinline__ void ldsm_x4_t(uint32_t r[4], uint32_t addr) {
    asm volatile("ldmatrix.sync.aligned.m8n8.x4.trans.shared.b16 {%0,%1,%2,%3}, [%4];"
                 : "=r"(r[0]), "=r"(r[1]), "=r"(r[2]), "=r"(r[3]) : "r"(addr));
}
__device__ __forceinline__ uint32_t pack_h2(float x, float y) {
    __half2 h = __float22half2_rn(make_float2(x, y));
    return *(uint32_t*)&h;
}

// ---------------------------------------------------------------------------
// Merged f32->fp16 convert (q,k,v,W*) + mask scan. grid (2048,1,8), 256 thr.
// ---------------------------------------------------------------------------
__global__ __launch_bounds__(256)
void round_all(const float* __restrict__ q, const float* __restrict__ k,
               const float* __restrict__ v, const float* __restrict__ Wq,
               const float* __restrict__ Wk, const float* __restrict__ Wv,
               const float* __restrict__ Wd, const float* __restrict__ mask)
{
    const int z = blockIdx.z;
    const int tid = threadIdx.x;
    if (z == 7) {   // mask scan
        const float4* m4 = (const float4*)mask;
        const size_t base = (size_t)blockIdx.x * 2048 + tid;
        bool nz = false;
#pragma unroll
        for (int i = 0; i < 8; i++) {
            float4 vv = m4[base + (size_t)i * 256];
            nz |= (vv.x != 0.f) | (vv.y != 0.f) | (vv.z != 0.f) | (vv.w != 0.f);
        }
        if (__syncthreads_or(nz) && tid == 0) atomicExch(&g_maskflag, 1);
        return;
    }
    const float* src; __half* dst; int nblk;
    switch (z) {
        case 0: src = q;  dst = g_RQ;    nblk = 2048; break;
        case 1: src = k;  dst = g_RK;    nblk = 2048; break;
        case 2: src = v;  dst = g_RV;    nblk = 2048; break;
        case 3: src = Wq; dst = g_RW[0]; nblk = 256;  break;
        case 4: src = Wk; dst = g_RW[1]; nblk = 256;  break;
        case 5: src = Wv; dst = g_RW[2]; nblk = 256;  break;
        default: src = Wd; dst = g_RW[3]; nblk = 256; break;
    }
    if (blockIdx.x >= (unsigned)nblk) return;
    const float4* s4 = (const float4*)src;
    __half2* d2 = (__half2*)dst;
    const size_t base = (size_t)blockIdx.x * 1024 + tid;
#pragma unroll
    for (int i = 0; i < 4; i++) {
        const size_t f = base + (size_t)i * 256;
        float4 vv = s4[f];
        d2[2 * f]     = __float22half2_rn(make_float2(vv.x, vv.y));
        d2[2 * f + 1] = __float22half2_rn(make_float2(vv.z, vv.w));
    }
}

// ---------------------------------------------------------------------------
// fp16 GEMM core (round-11 config, the proven optimum): BM=BN=128, BK=32
// halves, 128 thr (2x2 warps, 64x64 warp tile), 4-stage pipe, per-chunk ldsm.
// ---------------------------------------------------------------------------
#define PSTH 40
#define STG_H (2 * 128 * PSTH)
#define STG_B (STG_H * 2)
#define GEMM_SMEM (4 * STG_B)         // 81920 bytes

template<int LAYOUT>
__device__ __forceinline__
void gemm_core(const __half* __restrict__ A, const __half* __restrict__ W,
               void* __restrict__ Cv, float scale, char* smc)
{
    const int tid = threadIdx.x;
    const int lane = tid & 31, wid = tid >> 5;
    const int wr = wid >> 1, wc = wid & 1;
    const int r0 = lane >> 2, c0 = lane & 3;
    const int g = lane >> 3, lr = lane & 7;
    const int row0 = blockIdx.x * 128, col0 = blockIdx.y * 128;
    const uint32_t smb = smem_u32(smc);

    const int aoff = (wr * 64 + lr + (g & 1) * 8) * PSTH + (g >> 1) * 8;
    const int boff = (wc * 64 + lr + (g >> 1) * 8) * PSTH + (g & 1) * 8;

    float acc[4][8][4];
#pragma unroll
    for (int mt = 0; mt < 4; mt++)
#pragma unroll
        for (int nt = 0; nt < 8; nt++)
#pragma unroll
            for (int j = 0; j < 4; j++) acc[mt][nt][j] = 0.f;

    auto load_stage = [&](int kt, int s) {
        uint32_t a_s = smb + s * STG_B;
        uint32_t b_s = a_s + 128 * PSTH * 2;
#pragma unroll
        for (int i = 0; i < 4; i++) {
            int c = tid + 128 * i;
            int row = c >> 2, c4 = c & 3;
            uint32_t so = (uint32_t)(row * PSTH + c4 * 8) * 2;
            cp16(a_s + so, A + (size_t)(row0 + row) * DIM + kt * 32 + c4 * 8);
            cp16(b_s + so, W + (size_t)(col0 + row) * DIM + kt * 32 + c4 * 8);
        }
    };

    load_stage(0, 0); CP_COMMIT();
    load_stage(1, 1); CP_COMMIT();
    load_stage(2, 2); CP_COMMIT();

    const int NT = DIM / 32;
    for (int kt = 0; kt < NT; kt++) {
        asm volatile("cp.async.wait_group 2;" ::: "memory");
        __syncthreads();
        if (kt + 3 < NT) load_stage(kt + 3, (kt + 3) & 3);
        CP_COMMIT();

        const uint32_t a_s = smb + (kt & 3) * STG_B;
        const uint32_t b_s = a_s + 128 * PSTH * 2;

        uint32_t a[2][4][4], bp[2][4][4];
#pragma unroll
        for (int ks = 0; ks < 2; ks++) {
            const int kb = ks * 16;
#pragma unroll
            for (int mt = 0; mt < 4; mt++)
                ldsm_x4(a[ks][mt], a_s + (uint32_t)(aoff + mt * 16 * PSTH + kb) * 2);
#pragma unroll
            for (int p = 0; p < 4; p++)
                ldsm_x4(bp[ks][p], b_s + (uint32_t)(boff + p * 16 * PSTH + kb) * 2);
        }
#pragma unroll
        for (int ks = 0; ks < 2; ks++)
#pragma unroll
            for (int nt = 0; nt < 8; nt++) {
                const uint32_t bfr[2] = { bp[ks][nt >> 1][(nt & 1) * 2],
                                          bp[ks][nt >> 1][(nt & 1) * 2 + 1] };
#pragma unroll
                for (int mt = 0; mt < 4; mt++)
                    mma_f16(acc[mt][nt], a[ks][mt], bfr);
            }
    }

#pragma unroll
    for (int mt = 0; mt < 4; mt++) {
        const int rA = row0 + wr * 64 + mt * 16 + r0;
#pragma unroll
        for (int rr = 0; rr < 2; rr++) {
            const int r = rA + rr * 8;
#pragma unroll
            for (int nt = 0; nt < 8; nt++) {
                const int col = col0 + wc * 64 + nt * 8 + 2 * c0;
                float v0 = acc[mt][nt][rr * 2 + 0] * scale;
                float v1 = acc[mt][nt][rr * 2 + 1] * scale;
                if (LAYOUT == 0) {
                    const int b = r >> 11, s = r & (SS - 1);
                    const int h = col >> 6, d = col & 63;
                    __half* C = (__half*)Cv;
                    *(__half2*)(C + ((size_t)((b * NH + h) * SS) + s) * HD + d) =
                        __float22half2_rn(make_float2(v0, v1));
                } else {
                    float* C = (float*)Cv;
                    *(float2*)(C + (size_t)r * DIM + col) = make_float2(v0, v1);
                }
            }
        }
    }
}

__global__ __launch_bounds__(128, 2)
void qkv_gemm()
{
    extern __shared__ char smc[];
    const int z = blockIdx.z;
    if (z == 0)      gemm_core<0>(g_RQ, g_RW[0], g_Q, 0.125f * LOG2E, smc);
    else if (z == 1) gemm_core<0>(g_RK, g_RW[1], g_K, 1.0f, smc);
    else             gemm_core<0>(g_RV, g_RW[2], g_V, 1.0f, smc);
}

__global__ __launch_bounds__(128, 2)
void out_gemm(float* __restrict__ C)
{
    extern __shared__ char smc[];
    gemm_core<1>(g_Z, g_RW[3], C, 1.0f, smc);
    if (blockIdx.x == 0 && blockIdx.y == 0 && threadIdx.x == 0)
        g_maskflag = 0;
}

// ---------------------------------------------------------------------------
// fp16 mma flash attention: 64-key tiles, base-2 softmax, P in registers,
// pipelined K/V ldsm, K/V cp.async ring deepened to 3 STAGES.
// CTA: 128 thr (4 warps), 128 q-rows (32/warp, mt=2), 32 iters of 64 keys.
// ---------------------------------------------------------------------------
#define KSTH 72                       // halves per row (64 + 8)
#define KS_H (64 * KSTH)              // 4608 halves per K (or V) stage
#define ATTN_SMEM ((3*KS_H + 3*KS_H) * 2)   // 55296 B

__global__ __launch_bounds__(128, 2)
void attn_mma(const float* __restrict__ mask)
{
    extern __shared__ char smc[];
    __half* Ks = (__half*)smc;                 // 3 stages (also Q staging area)
    __half* Vs = Ks + 3 * KS_H;                // 3 stages
    const uint32_t ks_b = smem_u32(Ks);
    const uint32_t vs_b = smem_u32(Vs);

    const int tid = threadIdx.x, lane = tid & 31, w = tid >> 5;
    const int r0 = lane >> 2, c0 = lane & 3;
    const int g = lane >> 3, lr = lane & 7;
    const int q0 = blockIdx.x * 128;
    const int bh = blockIdx.y, b = bh >> 4, h = bh & 15;
    const int use_mask = g_maskflag;

    const int qAoff = (w * 32 + lr + (g & 1) * 8) * KSTH + (g >> 1) * 8;  // A-style Q
    const int kBoff = (lr + (g >> 1) * 8) * KSTH + (g & 1) * 8;           // B-style K
    const int vBoff = (lr + (g & 1) * 8) * KSTH + (g >> 1) * 8;           // trans-B V

    const __half* Kg0 = g_K + (size_t)bh * SS * HD;
    const __half* Vg0 = g_V + (size_t)bh * SS * HD;

    // stage Q tile (128 x 64 halves) into Ks area, pull A-frags
    const __half* Qg = g_Q + ((size_t)bh * SS + q0) * HD;
#pragma unroll
    for (int i = 0; i < 8; i++) {
        int c = tid + 128 * i;
        int row = c >> 3, c8 = c & 7;
        *(uint4*)(Ks + row * KSTH + c8 * 8) = *(const uint4*)(Qg + (size_t)row * HD + c8 * 8);
    }
    __syncthreads();
    uint32_t qf[2][4][4];
#pragma unroll
    for (int mt = 0; mt < 2; mt++)
#pragma unroll
        for (int kc = 0; kc < 4; kc++)
            ldsm_x4(qf[mt][kc], ks_b + (uint32_t)(qAoff + mt * 16 * KSTH + kc * 16) * 2);
    __syncthreads();   // Q reads done before K/V loads overwrite

    float o[2][8][4];
#pragma unroll
    for (int mt = 0; mt < 2; mt++)
#pragma unroll
        for (int nt = 0; nt < 8; nt++)
#pragma unroll
            for (int j = 0; j < 4; j++) o[mt][nt][j] = 0.f;
    float mrow[2][2], lrow[2][2];
#pragma unroll
    for (int mt = 0; mt < 2; mt++) { mrow[mt][0] = mrow[mt][1] = -INFINITY;
                                     lrow[mt][0] = lrow[mt][1] = 0.f; }

    auto load_kv = [&](int t, int s) {
#pragma unroll
        for (int i = 0; i < 4; i++) {
            int c = tid + 128 * i;               // 0..511
            int row = c >> 3, c8 = c & 7;
            cp16(ks_b + (uint32_t)(s * KS_H + row * KSTH + c8 * 8) * 2,
                 Kg0 + (size_t)(t * 64 + row) * HD + c8 * 8);
            cp16(vs_b + (uint32_t)(s * KS_H + row * KSTH + c8 * 8) * 2,
                 Vg0 + (size_t)(t * 64 + row) * HD + c8 * 8);
        }
    };

    load_kv(0, 0); CP_COMMIT();
    load_kv(1, 1); CP_COMMIT();

    const int NIT = SS / 64;                     // 32
    int st = 0;                                  // stage of tile it
    for (int it = 0; it < NIT; it++) {
        if (it + 2 < NIT) {
            int ps = st + 2; if (ps >= 3) ps -= 3;
            load_kv(it + 2, ps);
        }
        CP_COMMIT();
        asm volatile("cp.async.wait_group 2;" ::: "memory");   // tile it resident
        __syncthreads();

        const uint32_t ksb = ks_b + (uint32_t)(st * KS_H) * 2;
        const uint32_t vsb = vs_b + (uint32_t)(st * KS_H) * 2;

        // ---- S = Q @ K^T (per warp: 32 x 64), pipelined K ldsm ----
        float s[2][8][4];
#pragma unroll
        for (int mt = 0; mt < 2; mt++)
#pragma unroll
            for (int nt = 0; nt < 8; nt++)
#pragma unroll
                for (int j = 0; j < 4; j++) s[mt][nt][j] = 0.f;

        uint32_t kp[2][4];
        ldsm_x4(kp[0], ksb + (uint32_t)(kBoff) * 2);   // (kc=0, p=0)
#pragma unroll
        for (int idx = 0; idx < 16; idx++) {
            const int kc = idx >> 2, p = idx & 3;
            if (idx + 1 < 16) {
                const int nkc = (idx + 1) >> 2, np = (idx + 1) & 3;
                ldsm_x4(kp[(idx + 1) & 1],
                        ksb + (uint32_t)(kBoff + np * 16 * KSTH + nkc * 16) * 2);
            }
            const uint32_t* kk = kp[idx & 1];
            const uint32_t f0[2] = { kk[0], kk[1] };
            const uint32_t f1[2] = { kk[2], kk[3] };
            mma_f16(s[0][2 * p],     qf[0][kc], f0);
            mma_f16(s[1][2 * p],     qf[1][kc], f0);
            mma_f16(s[0][2 * p + 1], qf[0][kc], f1);
            mma_f16(s[1][2 * p + 1], qf[1][kc], f1);
        }

        if (use_mask) {
#pragma unroll
            for (int mt = 0; mt < 2; mt++) {
                const float* Mg = mask + ((size_t)b * SS + (q0 + w * 32 + mt * 16 + r0)) * SS
                                       + it * 64;
#pragma unroll
                for (int nt = 0; nt < 8; nt++) {
                    float2 mlo = *(const float2*)(Mg + nt * 8 + 2 * c0);
                    float2 mhi = *(const float2*)(Mg + (size_t)8 * SS + nt * 8 + 2 * c0);
                    s[mt][nt][0] = fmaf(mlo.x, LOG2E, s[mt][nt][0]);
                    s[mt][nt][1] = fmaf(mlo.y, LOG2E, s[mt][nt][1]);
                    s[mt][nt][2] = fmaf(mhi.x, LOG2E, s[mt][nt][2]);
                    s[mt][nt][3] = fmaf(mhi.y, LOG2E, s[mt][nt][3]);
                }
            }
        }

        // ---- online softmax (base-2); P packed into A-frags in registers ----
        uint32_t pf[2][4][4];
#pragma unroll
        for (int mt = 0; mt < 2; mt++) {
            float mx_lo = -INFINITY, mx_hi = -INFINITY;
#pragma unroll
            for (int nt = 0; nt < 8; nt++) {
                mx_lo = fmaxf(mx_lo, fmaxf(s[mt][nt][0], s[mt][nt][1]));
                mx_hi = fmaxf(mx_hi, fmaxf(s[mt][nt][2], s[mt][nt][3]));
            }
            mx_lo = fmaxf(mx_lo, __shfl_xor_sync(0xffffffffu, mx_lo, 1));
            mx_lo = fmaxf(mx_lo, __shfl_xor_sync(0xffffffffu, mx_lo, 2));
            mx_hi = fmaxf(mx_hi, __shfl_xor_sync(0xffffffffu, mx_hi, 1));
            mx_hi = fmaxf(mx_hi, __shfl_xor_sync(0xffffffffu, mx_hi, 2));
            const float nm_lo = fmaxf(mrow[mt][0], mx_lo);
            const float nm_hi = fmaxf(mrow[mt][1], mx_hi);
            const float corr_lo = exp2f(mrow[mt][0] - nm_lo);
            const float corr_hi = exp2f(mrow[mt][1] - nm_hi);
            mrow[mt][0] = nm_lo; mrow[mt][1] = nm_hi;

            float sum_lo = 0.f, sum_hi = 0.f;
#pragma unroll
            for (int nt = 0; nt < 8; nt++) {
                float p0 = exp2f(s[mt][nt][0] - nm_lo);
                float p1 = exp2f(s[mt][nt][1] - nm_lo);
                float p2 = exp2f(s[mt][nt][2] - nm_hi);
                float p3 = exp2f(s[mt][nt][3] - nm_hi);
                sum_lo += p0 + p1; sum_hi += p2 + p3;
                const int kc = nt >> 1, base = (nt & 1) * 2;
                pf[mt][kc][base + 0] = pack_h2(p0, p1);
                pf[mt][kc][base + 1] = pack_h2(p2, p3);
            }
            sum_lo += __shfl_xor_sync(0xffffffffu, sum_lo, 1);
            sum_lo += __shfl_xor_sync(0xffffffffu, sum_lo, 2);
            sum_hi += __shfl_xor_sync(0xffffffffu, sum_hi, 1);
            sum_hi += __shfl_xor_sync(0xffffffffu, sum_hi, 2);
            lrow[mt][0] = lrow[mt][0] * corr_lo + sum_lo;
            lrow[mt][1] = lrow[mt][1] * corr_hi + sum_hi;
#pragma unroll
            for (int nt = 0; nt < 8; nt++) {
                o[mt][nt][0] *= corr_lo; o[mt][nt][1] *= corr_lo;
                o[mt][nt][2] *= corr_hi; o[mt][nt][3] *= corr_hi;
            }
        }

        // ---- O += P @ V (per warp: 32 x 64, k=64), pipelined V ldsm ----
        uint32_t vp[2][4];
        ldsm_x4_t(vp[0], vsb + (uint32_t)(vBoff) * 2);   // (kc=0, dp=0)
#pragma unroll
        for (int idx = 0; idx < 16; idx++) {
            const int kc = idx >> 2, dp = idx & 3;
            if (idx + 1 < 16) {
                const int nkc = (idx + 1) >> 2, ndp = (idx + 1) & 3;
                ldsm_x4_t(vp[(idx + 1) & 1],
                          vsb + (uint32_t)(vBoff + nkc * 16 * KSTH + ndp * 16) * 2);
            }
            const uint32_t* vv = vp[idx & 1];
            const uint32_t f0[2] = { vv[0], vv[1] };
            const uint32_t f1[2] = { vv[2], vv[3] };
            mma_f16(o[0][2 * dp],     pf[0][kc], f0);
            mma_f16(o[1][2 * dp],     pf[1][kc], f0);
            mma_f16(o[0][2 * dp + 1], pf[0][kc], f1);
            mma_f16(o[1][2 * dp + 1], pf[1][kc], f1);
        }
        __syncthreads();   // all warps done with stage st before it's reloaded
        if (++st == 3) st = 0;
    }

    // epilogue: normalize, write fp16 Z[b*SS+q][h*HD+d]
#pragma unroll
    for (int mt = 0; mt < 2; mt++) {
        const float inv_lo = 1.f / lrow[mt][0], inv_hi = 1.f / lrow[mt][1];
        const int qlo = q0 + w * 32 + mt * 16 + r0;
        __half* Zlo = g_Z + ((size_t)b * SS + qlo) * DIM + h * HD;
        __half* Zhi = Zlo + (size_t)8 * DIM;
#pragma unroll
        for (int nt = 0; nt < 8; nt++) {
            const int d = nt * 8 + 2 * c0;
            *(__half2*)(Zlo + d) =
                __float22half2_rn(make_float2(o[mt][nt][0] * inv_lo, o[mt][nt][1] * inv_lo));
            *(__half2*)(Zhi + d) =
                __float22half2_rn(make_float2(o[mt][nt][2] * inv_hi, o[mt][nt][3] * inv_hi));
        }
    }
}

// ---------------------------------------------------------------------------
extern "C" void kernel_launch(void* const* d_in, const int* in_sizes, int n_in,
                              void* d_out, int out_size)
{
    const float* q    = (const float*)d_in[0];
    const float* k    = (const float*)d_in[1];
    const float* v    = (const float*)d_in[2];
    const float* mask = (const float*)d_in[3];
    const float* Wq   = (const float*)d_in[4];
    const float* Wk   = (const float*)d_in[5];
    const float* Wv   = (const float*)d_in[6];
    const float* Wd   = (const float*)d_in[7];

    cudaFuncSetAttribute(qkv_gemm, cudaFuncAttributeMaxDynamicSharedMemorySize, GEMM_SMEM);
    cudaFuncSetAttribute(out_gemm, cudaFuncAttributeMaxDynamicSharedMemorySize, GEMM_SMEM);
    cudaFuncSetAttribute(attn_mma, cudaFuncAttributeMaxDynamicSharedMemorySize, ATTN_SMEM);

    // launch 1: f32->fp16 convert everything + mask scan
    round_all<<<dim3(2048, 1, 8), 256>>>(q, k, v, Wq, Wk, Wv, Wd, mask);

    // launch 2: q/k/v projections (fp16 mma; Q pre-scaled by 0.125*log2e)
    qkv_gemm<<<dim3(MROWS/128, DIM/128, 3), 128, GEMM_SMEM>>>();

    // launch 3: flash attention (fp16 mma, base-2 softmax, P in registers)
    attn_mma<<<dim3(SS/128, BB*NH), 128, ATTN_SMEM>>>(mask);

    // launch 4: output projection, f32 out (+ maskflag reset)
    out_gemm<<<dim3(MROWS/128, DIM/128), 128, GEMM_SMEM>>>((float*)d_out);
}

// round 15
// speedup vs baseline: 1.7090x; 1.0377x over previous
#include <cuda_runtime.h>
#include <cuda_fp16.h>
#include <math.h>
#include <stdint.h>

#define DIM 1024
#define BB 4
#define SS 2048
#define NH 16
#define HD 64
#define MROWS (BB*SS)   // 8192
#define LOG2E 1.44269504088896340736f

// ---------------------------------------------------------------------------
// Scratch (device globals; no allocation allowed) — fp16 operands everywhere
// ---------------------------------------------------------------------------
__device__ __half g_Q[BB*NH*SS*HD];   // [b,h,s,d] projected Q (x 0.125*log2e)
__device__ __half g_K[BB*NH*SS*HD];
__device__ __half g_V[BB*NH*SS*HD];
__device__ __half g_Z[MROWS*DIM];     // attention out
__device__ __half g_RQ[MROWS*DIM];    // fp16 inputs
__device__ __half g_RK[MROWS*DIM];
__device__ __half g_RV[MROWS*DIM];
__device__ __half g_RW[4][DIM*DIM];   // fp16 weights
__device__ int    g_maskflag;         // zero-init; reset by out_gemm each run

// ---------------------------------------------------------------------------
// Helpers (compute_103-legal, sm_80-era PTX)
// ---------------------------------------------------------------------------
__device__ __forceinline__ uint32_t smem_u32(const void* p) {
    uint32_t a;
    asm("{ .reg .u64 t; cvta.to.shared.u64 t, %1; cvt.u32.u64 %0, t; }" : "=r"(a) : "l"(p));
    return a;
}
__device__ __forceinline__ void cp16(uint32_t dst, const void* src) {
    asm volatile("cp.async.cg.shared.global [%0], [%1], 16;" :: "r"(dst), "l"(src));
}
#define CP_COMMIT() asm volatile("cp.async.commit_group;" ::: "memory")

__device__ __forceinline__ void mma_f16(float d[4], const uint32_t a[4], const uint32_t b[2]) {
    asm volatile(
        "mma.sync.aligned.m16n8k16.row.col.f32.f16.f16.f32 "
        "{%0,%1,%2,%3}, {%4,%5,%6,%7}, {%8,%9}, {%0,%1,%2,%3};"
        : "+f"(d[0]), "+f"(d[1]), "+f"(d[2]), "+f"(d[3])
        : "r"(a[0]), "r"(a[1]), "r"(a[2]), "r"(a[3]), "r"(b[0]), "r"(b[1]));
}
__device__ __forceinline__ void ldsm_x4(uint32_t r[4], uint32_t addr) {
    asm volatile("ldmatrix.sync.aligned.m8n8.x4.shared.b16 {%0,%1,%2,%3}, [%4];"
                 : "=r"(r[0]), "=r"(r[1]), "=r"(r[2]), "=r"(r[3]) : "r"(addr));
}
__device__ __forceinline__ void ldsm_x4_t(uint32_t r[4], uint32_t addr) {
    asm volatile("ldmatrix.sync.aligned.m8n8.x4.trans.shared.b16 {%0,%1,%2,%3}, [%4];"
                 : "=r"(r[0]), "=r"(r[1]), "=r"(r[2]), "=r"(r[3]) : "r"(addr));
}
__device__ __forceinline__ uint32_t pack_h2(float x, float y) {
    __half2 h = __float22half2_rn(make_float2(x, y));
    return *(uint32_t*)&h;
}

// ---------------------------------------------------------------------------
// Slim f32->fp16 convert: grid (2048,1,4), 256 thr.
// z=0/1/2: q/k/v inputs (2048 blocks each); z=3: all 4 weights (4x256 blocks).
// ---------------------------------------------------------------------------
__global__ __launch_bounds__(256)
void round_all(const float* __restrict__ q, const float* __restrict__ k,
               const float* __restrict__ v, const float* __restrict__ Wq,
               const float* __restrict__ Wk, const float* __restrict__ Wv,
               const float* __restrict__ Wd)
{
    const int z = blockIdx.z;
    const int tid = threadIdx.x;
    const float* src; __half* dst; unsigned bx = blockIdx.x;
    if (z == 3) {
        if (bx >= 1024) return;
        const int wsel = bx >> 8;                // 0..3
        bx &= 255;
        switch (wsel) {
            case 0: src = Wq; dst = g_RW[0]; break;
            case 1: src = Wk; dst = g_RW[1]; break;
            case 2: src = Wv; dst = g_RW[2]; break;
            default: src = Wd; dst = g_RW[3]; break;
        }
    } else {
        src = (z == 0) ? q : (z == 1) ? k : v;
        dst = (z == 0) ? g_RQ : (z == 1) ? g_RK : g_RV;
    }
    const float4* s4 = (const float4*)src;
    __half2* d2 = (__half2*)dst;
    const size_t base = (size_t)bx * 1024 + tid;
#pragma unroll
    for (int i = 0; i < 4; i++) {
        const size_t f = base + (size_t)i * 256;
        float4 vv = s4[f];
        d2[2 * f]     = __float22half2_rn(make_float2(vv.x, vv.y));
        d2[2 * f + 1] = __float22half2_rn(make_float2(vv.z, vv.w));
    }
}

// ---------------------------------------------------------------------------
// fp16 GEMM core (round-11 config, the proven optimum): BM=BN=128, BK=32
// halves, 128 thr (2x2 warps, 64x64 warp tile), 4-stage pipe, per-chunk ldsm.
// ---------------------------------------------------------------------------
#define PSTH 40
#define STG_H (2 * 128 * PSTH)
#define STG_B (STG_H * 2)
#define GEMM_SMEM (4 * STG_B)         // 81920 bytes

template<int LAYOUT>
__device__ __forceinline__
void gemm_core(const __half* __restrict__ A, const __half* __restrict__ W,
               void* __restrict__ Cv, float scale, char* smc)
{
    const int tid = threadIdx.x;
    const int lane = tid & 31, wid = tid >> 5;
    const int wr = wid >> 1, wc = wid & 1;
    const int r0 = lane >> 2, c0 = lane & 3;
    const int g = lane >> 3, lr = lane & 7;
    const int row0 = blockIdx.x * 128, col0 = blockIdx.y * 128;
    const uint32_t smb = smem_u32(smc);

    const int aoff = (wr * 64 + lr + (g & 1) * 8) * PSTH + (g >> 1) * 8;
    const int boff = (wc * 64 + lr + (g >> 1) * 8) * PSTH + (g & 1) * 8;

    float acc[4][8][4];
#pragma unroll
    for (int mt = 0; mt < 4; mt++)
#pragma unroll
        for (int nt = 0; nt < 8; nt++)
#pragma unroll
            for (int j = 0; j < 4; j++) acc[mt][nt][j] = 0.f;

    auto load_stage = [&](int kt, int s) {
        uint32_t a_s = smb + s * STG_B;
        uint32_t b_s = a_s + 128 * PSTH * 2;
#pragma unroll
        for (int i = 0; i < 4; i++) {
            int c = tid + 128 * i;
            int row = c >> 2, c4 = c & 3;
            uint32_t so = (uint32_t)(row * PSTH + c4 * 8) * 2;
            cp16(a_s + so, A + (size_t)(row0 + row) * DIM + kt * 32 + c4 * 8);
            cp16(b_s + so, W + (size_t)(col0 + row) * DIM + kt * 32 + c4 * 8);
        }
    };

    load_stage(0, 0); CP_COMMIT();
    load_stage(1, 1); CP_COMMIT();
    load_stage(2, 2); CP_COMMIT();

    const int NT = DIM / 32;
    for (int kt = 0; kt < NT; kt++) {
        asm volatile("cp.async.wait_group 2;" ::: "memory");
        __syncthreads();
        if (kt + 3 < NT) load_stage(kt + 3, (kt + 3) & 3);
        CP_COMMIT();

        const uint32_t a_s = smb + (kt & 3) * STG_B;
        const uint32_t b_s = a_s + 128 * PSTH * 2;

        uint32_t a[2][4][4], bp[2][4][4];
#pragma unroll
        for (int ks = 0; ks < 2; ks++) {
            const int kb = ks * 16;
#pragma unroll
            for (int mt = 0; mt < 4; mt++)
                ldsm_x4(a[ks][mt], a_s + (uint32_t)(aoff + mt * 16 * PSTH + kb) * 2);
#pragma unroll
            for (int p = 0; p < 4; p++)
                ldsm_x4(bp[ks][p], b_s + (uint32_t)(boff + p * 16 * PSTH + kb) * 2);
        }
#pragma unroll
        for (int ks = 0; ks < 2; ks++)
#pragma unroll
            for (int nt = 0; nt < 8; nt++) {
                const uint32_t bfr[2] = { bp[ks][nt >> 1][(nt & 1) * 2],
                                          bp[ks][nt >> 1][(nt & 1) * 2 + 1] };
#pragma unroll
                for (int mt = 0; mt < 4; mt++)
                    mma_f16(acc[mt][nt], a[ks][mt], bfr);
            }
    }

#pragma unroll
    for (int mt = 0; mt < 4; mt++) {
        const int rA = row0 + wr * 64 + mt * 16 + r0;
#pragma unroll
        for (int rr = 0; rr < 2; rr++) {
            const int r = rA + rr * 8;
#pragma unroll
            for (int nt = 0; nt < 8; nt++) {
                const int col = col0 + wc * 64 + nt * 8 + 2 * c0;
                float v0 = acc[mt][nt][rr * 2 + 0] * scale;
                float v1 = acc[mt][nt][rr * 2 + 1] * scale;
                if (LAYOUT == 0) {
                    const int b = r >> 11, s = r & (SS - 1);
                    const int h = col >> 6, d = col & 63;
                    __half* C = (__half*)Cv;
                    *(__half2*)(C + ((size_t)((b * NH + h) * SS) + s) * HD + d) =
                        __float22half2_rn(make_float2(v0, v1));
                } else {
                    float* C = (float*)Cv;
                    *(float2*)(C + (size_t)r * DIM + col) = make_float2(v0, v1);
                }
            }
        }
    }
}

// grid (64, 8, 4): z=0/1/2 Q/K/V projections; z=3 mask scan (512 CTAs),
// overlapped with the compute-bound GEMM slices.
__global__ __launch_bounds__(128, 2)
void qkv_gemm(const float* __restrict__ mask)
{
    extern __shared__ char smc[];
    const int z = blockIdx.z;
    if (z == 3) {
        const float4* m4 = (const float4*)mask;
        const int cta = blockIdx.y * 64 + blockIdx.x;        // 0..511
        const size_t base = (size_t)cta * 8192 + threadIdx.x;
        bool nz = false;
#pragma unroll 8
        for (int i = 0; i < 64; i++) {
            float4 vv = m4[base + (size_t)i * 128];
            nz |= (vv.x != 0.f) | (vv.y != 0.f) | (vv.z != 0.f) | (vv.w != 0.f);
        }
        if (__syncthreads_or(nz) && threadIdx.x == 0)
            atomicExch(&g_maskflag, 1);
        return;
    }
    if (z == 0)      gemm_core<0>(g_RQ, g_RW[0], g_Q, 0.125f * LOG2E, smc);
    else if (z == 1) gemm_core<0>(g_RK, g_RW[1], g_K, 1.0f, smc);
    else             gemm_core<0>(g_RV, g_RW[2], g_V, 1.0f, smc);
}

__global__ __launch_bounds__(128, 2)
void out_gemm(float* __restrict__ C)
{
    extern __shared__ char smc[];
    gemm_core<1>(g_Z, g_RW[3], C, 1.0f, smc);
    if (blockIdx.x == 0 && blockIdx.y == 0 && threadIdx.x == 0)
        g_maskflag = 0;   // for the next graph replay
}

// ---------------------------------------------------------------------------
// fp16 mma flash attention (round-11, the 452.9us version): 64-key tiles,
// base-2 softmax, P in registers, pipelined K/V ldsm, 2-stage cp.async.
// ---------------------------------------------------------------------------
#define KSTH 72                       // halves per row (64 + 8)
#define KS_H (64 * KSTH)              // 4608 halves per K (or V) stage
#define ATTN_SMEM ((2*KS_H + 2*KS_H) * 2)   // 36864 B

__global__ __launch_bounds__(128, 2)
void attn_mma(const float* __restrict__ mask)
{
    extern __shared__ char smc[];
    __half* Ks = (__half*)smc;
    __half* Vs = Ks + 2 * KS_H;
    const uint32_t ks_b = smem_u32(Ks);
    const uint32_t vs_b = smem_u32(Vs);

    const int tid = threadIdx.x, lane = tid & 31, w = tid >> 5;
    const int r0 = lane >> 2, c0 = lane & 3;
    const int g = lane >> 3, lr = lane & 7;
    const int q0 = blockIdx.x * 128;
    const int bh = blockIdx.y, b = bh >> 4, h = bh & 15;
    const int use_mask = g_maskflag;

    const int qAoff = (w * 32 + lr + (g & 1) * 8) * KSTH + (g >> 1) * 8;
    const int kBoff = (lr + (g >> 1) * 8) * KSTH + (g & 1) * 8;
    const int vBoff = (lr + (g & 1) * 8) * KSTH + (g >> 1) * 8;

    const __half* Kg0 = g_K + (size_t)bh * SS * HD;
    const __half* Vg0 = g_V + (size_t)bh * SS * HD;

    const __half* Qg = g_Q + ((size_t)bh * SS + q0) * HD;
#pragma unroll
    for (int i = 0; i < 8; i++) {
        int c = tid + 128 * i;
        int row = c >> 3, c8 = c & 7;
        *(uint4*)(Ks + row * KSTH + c8 * 8) = *(const uint4*)(Qg + (size_t)row * HD + c8 * 8);
    }
    __syncthreads();
    uint32_t qf[2][4][4];
#pragma unroll
    for (int mt = 0; mt < 2; mt++)
#pragma unroll
        for (int kc = 0; kc < 4; kc++)
            ldsm_x4(qf[mt][kc], ks_b + (uint32_t)(qAoff + mt * 16 * KSTH + kc * 16) * 2);
    __syncthreads();

    float o[2][8][4];
#pragma unroll
    for (int mt = 0; mt < 2; mt++)
#pragma unroll
        for (int nt = 0; nt < 8; nt++)
#pragma unroll
            for (int j = 0; j < 4; j++) o[mt][nt][j] = 0.f;
    float mrow[2][2], lrow[2][2];
#pragma unroll
    for (int mt = 0; mt < 2; mt++) { mrow[mt][0] = mrow[mt][1] = -INFINITY;
                                     lrow[mt][0] = lrow[mt][1] = 0.f; }

    auto load_kv = [&](int t, int s) {
#pragma unroll
        for (int i = 0; i < 4; i++) {
            int c = tid + 128 * i;
            int row = c >> 3, c8 = c & 7;
            cp16(ks_b + (uint32_t)(s * KS_H + row * KSTH + c8 * 8) * 2,
                 Kg0 + (size_t)(t * 64 + row) * HD + c8 * 8);
            cp16(vs_b + (uint32_t)(s * KS_H + row * KSTH + c8 * 8) * 2,
                 Vg0 + (size_t)(t * 64 + row) * HD + c8 * 8);
        }
    };

    load_kv(0, 0); CP_COMMIT();

    const int NIT = SS / 64;
    for (int it = 0; it < NIT; it++) {
        if (it + 1 < NIT) load_kv(it + 1, (it + 1) & 1);
        CP_COMMIT();
        asm volatile("cp.async.wait_group 1;" ::: "memory");
        __syncthreads();

        const uint32_t ksb = ks_b + (uint32_t)((it & 1) * KS_H) * 2;
        const uint32_t vsb = vs_b + (uint32_t)((it & 1) * KS_H) * 2;

        float s[2][8][4];
#pragma unroll
        for (int mt = 0; mt < 2; mt++)
#pragma unroll
            for (int nt = 0; nt < 8; nt++)
#pragma unroll
                for (int j = 0; j < 4; j++) s[mt][nt][j] = 0.f;

        uint32_t kp[2][4];
        ldsm_x4(kp[0], ksb + (uint32_t)(kBoff) * 2);
#pragma unroll
        for (int idx = 0; idx < 16; idx++) {
            const int kc = idx >> 2, p = idx & 3;
            if (idx + 1 < 16) {
                const int nkc = (idx + 1) >> 2, np = (idx + 1) & 3;
                ldsm_x4(kp[(idx + 1) & 1],
                        ksb + (uint32_t)(kBoff + np * 16 * KSTH + nkc * 16) * 2);
            }
            const uint32_t* kk = kp[idx & 1];
            const uint32_t f0[2] = { kk[0], kk[1] };
            const uint32_t f1[2] = { kk[2], kk[3] };
            mma_f16(s[0][2 * p],     qf[0][kc], f0);
            mma_f16(s[1][2 * p],     qf[1][kc], f0);
            mma_f16(s[0][2 * p + 1], qf[0][kc], f1);
            mma_f16(s[1][2 * p + 1], qf[1][kc], f1);
        }

        if (use_mask) {
#pragma unroll
            for (int mt = 0; mt < 2; mt++) {
                const float* Mg = mask + ((size_t)b * SS + (q0 + w * 32 + mt * 16 + r0)) * SS
                                       + it * 64;
#pragma unroll
                for (int nt = 0; nt < 8; nt++) {
                    float2 mlo = *(const float2*)(Mg + nt * 8 + 2 * c0);
                    float2 mhi = *(const float2*)(Mg + (size_t)8 * SS + nt * 8 + 2 * c0);
                    s[mt][nt][0] = fmaf(mlo.x, LOG2E, s[mt][nt][0]);
                    s[mt][nt][1] = fmaf(mlo.y, LOG2E, s[mt][nt][1]);
                    s[mt][nt][2] = fmaf(mhi.x, LOG2E, s[mt][nt][2]);
                    s[mt][nt][3] = fmaf(mhi.y, LOG2E, s[mt][nt][3]);
                }
            }
        }

        uint32_t pf[2][4][4];
#pragma unroll
        for (int mt = 0; mt < 2; mt++) {
            float mx_lo = -INFINITY, mx_hi = -INFINITY;
#pragma unroll
            for (int nt = 0; nt < 8; nt++) {
                mx_lo = fmaxf(mx_lo, fmaxf(s[mt][nt][0], s[mt][nt][1]));
                mx_hi = fmaxf(mx_hi, fmaxf(s[mt][nt][2], s[mt][nt][3]));
            }
            mx_lo = fmaxf(mx_lo, __shfl_xor_sync(0xffffffffu, mx_lo, 1));
            mx_lo = fmaxf(mx_lo, __shfl_xor_sync(0xffffffffu, mx_lo, 2));
            mx_hi = fmaxf(mx_hi, __shfl_xor_sync(0xffffffffu, mx_hi, 1));
            mx_hi = fmaxf(mx_hi, __shfl_xor_sync(0xffffffffu, mx_hi, 2));
            const float nm_lo = fmaxf(mrow[mt][0], mx_lo);
            const float nm_hi = fmaxf(mrow[mt][1], mx_hi);
            const float corr_lo = exp2f(mrow[mt][0] - nm_lo);
            const float corr_hi = exp2f(mrow[mt][1] - nm_hi);
            mrow[mt][0] = nm_lo; mrow[mt][1] = nm_hi;

            float sum_lo = 0.f, sum_hi = 0.f;
#pragma unroll
            for (int nt = 0; nt < 8; nt++) {
                float p0 = exp2f(s[mt][nt][0] - nm_lo);
                float p1 = exp2f(s[mt][nt][1] - nm_lo);
                float p2 = exp2f(s[mt][nt][2] - nm_hi);
                float p3 = exp2f(s[mt][nt][3] - nm_hi);
                sum_lo += p0 + p1; sum_hi += p2 + p3;
                const int kc = nt >> 1, base = (nt & 1) * 2;
                pf[mt][kc][base + 0] = pack_h2(p0, p1);
                pf[mt][kc][base + 1] = pack_h2(p2, p3);
            }
            sum_lo += __shfl_xor_sync(0xffffffffu, sum_lo, 1);
            sum_lo += __shfl_xor_sync(0xffffffffu, sum_lo, 2);
            sum_hi += __shfl_xor_sync(0xffffffffu, sum_hi, 1);
            sum_hi += __shfl_xor_sync(0xffffffffu, sum_hi, 2);
            lrow[mt][0] = lrow[mt][0] * corr_lo + sum_lo;
            lrow[mt][1] = lrow[mt][1] * corr_hi + sum_hi;
#pragma unroll
            for (int nt = 0; nt < 8; nt++) {
                o[mt][nt][0] *= corr_lo; o[mt][nt][1] *= corr_lo;
                o[mt][nt][2] *= corr_hi; o[mt][nt][3] *= corr_hi;
            }
        }

        uint32_t vp[2][4];
        ldsm_x4_t(vp[0], vsb + (uint32_t)(vBoff) * 2);
#pragma unroll
        for (int idx = 0; idx < 16; idx++) {
            const int kc = idx >> 2, dp = idx & 3;
            if (idx + 1 < 16) {
                const int nkc = (idx + 1) >> 2, ndp = (idx + 1) & 3;
                ldsm_x4_t(vp[(idx + 1) & 1],
                          vsb + (uint32_t)(vBoff + nkc * 16 * KSTH + ndp * 16) * 2);
            }
            const uint32_t* vv = vp[idx & 1];
            const uint32_t f0[2] = { vv[0], vv[1] };
            const uint32_t f1[2] = { vv[2], vv[3] };
            mma_f16(o[0][2 * dp],     pf[0][kc], f0);
            mma_f16(o[1][2 * dp],     pf[1][kc], f0);
            mma_f16(o[0][2 * dp + 1], pf[0][kc], f1);
            mma_f16(o[1][2 * dp + 1], pf[1][kc], f1);
        }
        __syncthreads();
    }

#pragma unroll
    for (int mt = 0; mt < 2; mt++) {
        const float inv_lo = 1.f / lrow[mt][0], inv_hi = 1.f / lrow[mt][1];
        const int qlo = q0 + w * 32 + mt * 16 + r0;
        __half* Zlo = g_Z + ((size_t)b * SS + qlo) * DIM + h * HD;
        __half* Zhi = Zlo + (size_t)8 * DIM;
#pragma unroll
        for (int nt = 0; nt < 8; nt++) {
            const int d = nt * 8 + 2 * c0;
            *(__half2*)(Zlo + d) =
                __float22half2_rn(make_float2(o[mt][nt][0] * inv_lo, o[mt][nt][1] * inv_lo));
            *(__half2*)(Zhi + d) =
                __float22half2_rn(make_float2(o[mt][nt][2] * inv_hi, o[mt][nt][3] * inv_hi));
        }
    }
}

// ---------------------------------------------------------------------------
extern "C" void kernel_launch(void* const* d_in, const int* in_sizes, int n_in,
                              void* d_out, int out_size)
{
    const float* q    = (const float*)d_in[0];
    const float* k    = (const float*)d_in[1];
    const float* v    = (const float*)d_in[2];
    const float* mask = (const float*)d_in[3];
    const float* Wq   = (const float*)d_in[4];
    const float* Wk   = (const float*)d_in[5];
    const float* Wv   = (const float*)d_in[6];
    const float* Wd   = (const float*)d_in[7];

    cudaFuncSetAttribute(qkv_gemm, cudaFuncAttributeMaxDynamicSharedMemorySize, GEMM_SMEM);
    cudaFuncSetAttribute(out_gemm, cudaFuncAttributeMaxDynamicSharedMemorySize, GEMM_SMEM);
    cudaFuncSetAttribute(attn_mma, cudaFuncAttributeMaxDynamicSharedMemorySize, ATTN_SMEM);

    // launch 1: f32->fp16 convert inputs + weights (slimmed, no scan)
    round_all<<<dim3(2048, 1, 4), 256>>>(q, k, v, Wq, Wk, Wv, Wd);

    // launch 2: q/k/v projections + mask scan overlapped (z=3)
    qkv_gemm<<<dim3(MROWS/128, DIM/128, 4), 128, GEMM_SMEM>>>(mask);

    // launch 3: flash attention (fp16 mma, base-2 softmax, P in registers)
    attn_mma<<<dim3(SS/128, BB*NH), 128, ATTN_SMEM>>>(mask);

    // launch 4: output projection, f32 out (+ maskflag reset)
    out_gemm<<<dim3(MROWS/128, DIM/128), 128, GEMM_SMEM>>>((float*)d_out);
}